// round 5
// baseline (speedup 1.0000x reference)
#include <cuda_runtime.h>

#define NB 8
#define NL 4096
#define NK 16
#define ND 128

#define TPB 512
#define WPB (TPB / 32)        // 16 warps = 16 queries per block
#define TILE 1024
#define NTILES (NL / TILE)
#define POOLCAP 224
#define SLOTS (POOLCAP / 32)  // 7 pool slots per lane

// scratch: neighbor indices (allocation-free rule -> __device__ global)
__device__ int g_nbr[NB * NL * NK];

__device__ __forceinline__ unsigned long long warp_min_u64(unsigned long long v)
{
#pragma unroll
    for (int o = 16; o; o >>= 1) {
        unsigned long long u = __shfl_xor_sync(0xffffffffu, v, o);
        v = (u < v) ? u : v;
    }
    return v;
}

// ---------------------------------------------------------------------------
// Warp-cooperative: extract the 16 smallest keys of pool[0..cnt) into
// pool[0..15] (ascending), keep survivors (d <= tau) at pool[16..), return
// new cnt and tau (= d of the 16th). Keys are unique => unique owners.
// ---------------------------------------------------------------------------
__device__ __forceinline__ int select16(unsigned long long* pool, int cnt,
                                        int lane, float* tau_out)
{
    unsigned long long s[SLOTS];
#pragma unroll
    for (int i = 0; i < SLOTS; ++i) {
        int idx = lane + 32 * i;
        s[i] = (idx < cnt) ? pool[idx] : ~0ull;
    }
    __syncwarp();
    unsigned long long kth = 0;
#pragma unroll
    for (int k = 0; k < NK; ++k) {
        unsigned long long lm = s[0];
#pragma unroll
        for (int i = 1; i < SLOTS; ++i) lm = (s[i] < lm) ? s[i] : lm;
        unsigned long long m = warp_min_u64(lm);
        if (lm == m) {                       // unique owner lane
#pragma unroll
            for (int i = 0; i < SLOTS; ++i)
                if (s[i] == m) { s[i] = ~0ull; break; }
        }
        if (lane == 0) pool[k] = m;          // all pool data lives in regs now
        kth = m;
    }
    const float tau = __uint_as_float((unsigned)(kth >> 32));

    // compact survivors (d <= tau) behind the sorted 16
    int base = NK;
#pragma unroll
    for (int i = 0; i < SLOTS; ++i) {
        float d = __uint_as_float((unsigned)(s[i] >> 32));
        bool keep = (s[i] != ~0ull) && (d <= tau);
        unsigned mk = __ballot_sync(0xffffffffu, keep);
        int pos = __popc(mk & ((1u << lane) - 1));
        if (keep) pool[base + pos] = s[i];
        base += __popc(mk);
    }
    __syncwarp();
    *tau_out = tau;
    return base;
}

// ---------------------------------------------------------------------------
// Kernel 1: brute-force 16-NN, ONE WARP PER QUERY. Lanes scan candidates in
// waves of 32; passing candidates go to a smem pool via ballot compaction;
// top-16 extracted warp-cooperatively.
// ---------------------------------------------------------------------------
__global__ __launch_bounds__(TPB)
void knn_kernel(const float* __restrict__ frame,
                float* __restrict__ eucl_out)
{
    __shared__ __align__(16) float4 tile[TILE];
    __shared__ unsigned long long pool[WPB][POOLCAP];

    const int tid  = threadIdx.x;
    const int warp = tid >> 5;
    const int lane = tid & 31;
    const int q    = blockIdx.x * WPB + warp;       // global query id
    const int b    = q / NL;
    const int ql   = q - b * NL;
    // frame rows are 48B = 3 float4's, 16B-aligned
    const float4* fb4 = (const float4*)frame + (size_t)b * NL * 3;
    const float*  fq  = frame + ((size_t)b * NL + ql) * 12;

    const float cx = fq[0], cy = fq[1], cz = fq[2];

    unsigned long long* mypool = pool[warp];
    int   cnt = 0;
    float tau = 3.0e38f;                            // warm-up: everything passes

    for (int t = 0; t < NTILES; ++t) {
        const int tb = t * TILE;
        __syncthreads();
        for (int i = tid; i < TILE; i += TPB)
            tile[i] = fb4[(size_t)(tb + i) * 3];    // (x,y,z,junk) per row
        __syncthreads();

#pragma unroll 4
        for (int w = 0; w < TILE / 32; ++w) {
            const int j = w * 32 + lane;
            float4 c = tile[j];
            // exact unfused IEEE rn arithmetic (matches XLA diff*diff -> sum)
            float dx = __fadd_rn(c.x, -cx);
            float dy = __fadd_rn(c.y, -cy);
            float dz = __fadd_rn(c.z, -cz);
            float d  = __fadd_rn(__fadd_rn(__fmul_rn(dx, dx), __fmul_rn(dy, dy)),
                                 __fmul_rn(dz, dz));
            bool pass = (d <= tau);
            unsigned mk = __ballot_sync(0xffffffffu, pass);
            if (mk) {                               // warp-uniform branch
                int pos = __popc(mk & ((1u << lane) - 1));
                if (pass)
                    mypool[cnt + pos] =
                        ((unsigned long long)__float_as_uint(d) << 32)
                        | (unsigned)(tb + j);
                cnt += __popc(mk);
                if (cnt > POOLCAP - 32) {           // refresh (rare; warm-up + tail)
                    __syncwarp();
                    cnt = select16(mypool, cnt, lane, &tau);
                }
            }
        }
    }
    __syncwarp();
    (void)select16(mypool, cnt, lane, &tau);        // final: pool[0..15] sorted

    // outputs: lanes 0..15 each handle one neighbor
    if (lane < NK) {
        unsigned long long key = mypool[lane];
        const int n = (int)(unsigned)key;
        const float* fn = frame + ((size_t)b * NL + n) * 12;
        float d0 = fn[0] - cx;
        float d1 = fn[1] - cy;
        float d2 = fn[2] - cz;
        // R[c][r] = fq[3 + c*3 + r]
        float R00 = fq[3],  R01 = fq[4],  R02 = fq[5];
        float R10 = fq[6],  R11 = fq[7],  R12 = fq[8];
        float R20 = fq[9],  R21 = fq[10], R22 = fq[11];

        const size_t base = (size_t)q * NK + lane;
        g_nbr[base] = n;
        float* eo = eucl_out + base * 3;
        eo[0] = d0 * R00 + d1 * R10 + d2 * R20;
        eo[1] = d0 * R01 + d1 * R11 + d2 * R21;
        eo[2] = d0 * R02 + d1 * R12 + d2 * R22;
    }
}

// ---------------------------------------------------------------------------
// Kernel 2: attribute gather (best measured config: 4 rows/warp, 8 lanes per
// row, 4 float4 per lane -> 44.8us).
// ---------------------------------------------------------------------------
__global__ __launch_bounds__(256, 8)
void gather_kernel(const float* __restrict__ attr,
                   float* __restrict__ gout)
{
    const int warp = (blockIdx.x * 256 + threadIdx.x) >> 5;
    const int lane = threadIdx.x & 31;
    const int row  = warp * 4 + (lane >> 3);      // 4 rows per warp
    const int l8   = lane & 7;

    const int b = row / (NL * NK);
    const int n = g_nbr[row];

    const float4* src = (const float4*)(attr + ((size_t)b * NL + n) * ND);
    float4*       dst = (float4*)(gout + (size_t)row * ND);

    float4 v0 = src[l8];
    float4 v1 = src[l8 + 8];
    float4 v2 = src[l8 + 16];
    float4 v3 = src[l8 + 24];
    dst[l8]      = v0;
    dst[l8 + 8]  = v1;
    dst[l8 + 16] = v2;
    dst[l8 + 24] = v3;
}

extern "C" void kernel_launch(void* const* d_in, const int* in_sizes, int n_in,
                              void* d_out, int out_size)
{
    const float* frame = (const float*)d_in[0];
    const float* attr  = (const float*)d_in[1];
    if (in_sizes[0] != NB * NL * 12) {
        frame = (const float*)d_in[1];
        attr  = (const float*)d_in[0];
    }

    float* eucl = (float*)d_out;                          // B*L*K*3 floats
    float* gath = (float*)d_out + (size_t)NB * NL * NK * 3;

    const int nq = NB * NL;                               // 32768 queries
    knn_kernel<<<nq / WPB, TPB>>>(frame, eucl);           // 2048 blocks x 512

    const int rows = NB * NL * NK;                        // 524288
    gather_kernel<<<rows / 32, 256>>>(attr, gath);        // 4 rows/warp
}

// round 6
// speedup vs baseline: 3.0143x; 3.0143x over previous
#include <cuda_runtime.h>

#define NB 8
#define NL 4096
#define NK 16
#define ND 128

#define QPB 64           // queries per block
#define TPB 128          // threads per block (2 threads per query)
#define TILE 1024        // candidates staged per smem tile
#define NTILES (NL / TILE)
#define BCAP 24          // per-thread candidate buffer capacity

// scratch: neighbor indices (allocation-free rule -> __device__ global)
__device__ int g_nbr[NB * NL * NK];

// ---------------------------------------------------------------------------
// sorted-ascending top-16 insert, split at the median. Strict '<' everywhere
// => stable (lower index wins ties within a thread's increasing-index scan).
// ---------------------------------------------------------------------------
__device__ __forceinline__ void ins16(float (&bd)[NK], int (&bi)[NK],
                                      float d, int j)
{
    if (d < bd[7]) {
#pragma unroll
        for (int i = 15; i > 8; --i) { bd[i] = bd[i - 1]; bi[i] = bi[i - 1]; }
        bd[8] = bd[7]; bi[8] = bi[7];
        float cd = d; int ci = j;
#pragma unroll
        for (int i = 0; i < 8; ++i) {
            if (cd < bd[i]) {
                float td = bd[i]; bd[i] = cd; cd = td;
                int   ti = bi[i]; bi[i] = ci; ci = ti;
            }
        }
    } else {
        float cd = d; int ci = j;
#pragma unroll
        for (int i = 8; i < 16; ++i) {
            if (cd < bd[i]) {
                float td = bd[i]; bd[i] = cd; cd = td;
                int   ti = bi[i]; bi[i] = ci; ci = ti;
            }
        }
    }
}

__device__ __forceinline__ unsigned long long pack2(float lo, float hi)
{
    unsigned long long r;
    asm("mov.b64 %0, {%1, %2};" : "=l"(r) : "f"(lo), "f"(hi));
    return r;
}

// packed squared-distance for one PAIR of candidates (exact unfused IEEE rn)
__device__ __forceinline__ void dist2(unsigned long long x2, unsigned long long y2,
                                      unsigned long long z2,
                                      unsigned long long ncx2, unsigned long long ncy2,
                                      unsigned long long ncz2,
                                      float& d0, float& d1)
{
    unsigned long long dx2, dy2, dz2, m0, m1, m2, s0, dd;
    asm("add.rn.f32x2 %0, %1, %2;" : "=l"(dx2) : "l"(x2), "l"(ncx2));
    asm("add.rn.f32x2 %0, %1, %2;" : "=l"(dy2) : "l"(y2), "l"(ncy2));
    asm("add.rn.f32x2 %0, %1, %2;" : "=l"(dz2) : "l"(z2), "l"(ncz2));
    asm("mul.rn.f32x2 %0, %1, %2;" : "=l"(m0) : "l"(dx2), "l"(dx2));
    asm("mul.rn.f32x2 %0, %1, %2;" : "=l"(m1) : "l"(dy2), "l"(dy2));
    asm("mul.rn.f32x2 %0, %1, %2;" : "=l"(m2) : "l"(dz2), "l"(dz2));
    asm("add.rn.f32x2 %0, %1, %2;" : "=l"(s0) : "l"(m0), "l"(m1));
    asm("add.rn.f32x2 %0, %1, %2;" : "=l"(dd) : "l"(s0), "l"(m2));
    asm("mov.b64 {%0, %1}, %2;" : "=f"(d0), "=f"(d1) : "l"(dd));
}

// ---------------------------------------------------------------------------
// Kernel 1: brute-force 16-NN, 2 threads per query (split-K), 8 candidates
// per iteration via LDS.128 + 4 independent packed f32x2 chains, predicated
// candidate buffering with warp-synchronized flushes, exact 2-way merge.
// ---------------------------------------------------------------------------
__global__ __launch_bounds__(TPB, 4)
void knn_kernel(const float* __restrict__ frame,
                float* __restrict__ eucl_out)
{
    __shared__ __align__(16) unsigned char smem_raw[16384];
    float* sx = (float*)smem_raw;            // TILE floats
    float* sy = sx + TILE;
    float* sz = sy + TILE;

    const int tid = threadIdx.x;
    const int h   = tid & 1;                 // which half of candidate space
    const int q   = blockIdx.x * QPB + (tid >> 1);   // global query id
    const int b   = q / NL;
    const int ql  = q - b * NL;
    const float* fb = frame + (size_t)b * NL * 12;   // [L][4][3]
    const float* fq = fb + ql * 12;

    const float cx = fq[0], cy = fq[1], cz = fq[2];
    const unsigned long long ncx2 = pack2(-cx, -cx);
    const unsigned long long ncy2 = pack2(-cy, -cy);
    const unsigned long long ncz2 = pack2(-cz, -cz);

    float bd[NK];
    int   bi[NK];
#pragma unroll
    for (int i = 0; i < NK; i++) { bd[i] = 3.0e38f; bi[i] = 0; }

    float2 lbuf[BCAP];                       // local-mem candidate buffer
    int    cnt = 0;
    float  tau = 3.0e38f;                    // stale copy of bd[15] (only shrinks)

    const float4* x4 = (const float4*)sx;
    const float4* y4 = (const float4*)sy;
    const float4* z4 = (const float4*)sz;

    for (int t = 0; t < NTILES; ++t) {
        const int tb = t * TILE;
        __syncthreads();
        {   // stage tile centers (rows are 48B = 3 x float4)
            const float4* src = (const float4*)(fb + (size_t)tb * 12);
            for (int i = tid; i < TILE; i += TPB) {
                float4 r = src[i * 3];       // (x, y, z, junk)
                sx[i] = r.x; sy[i] = r.y; sz[i] = r.z;
            }
        }
        __syncthreads();

        // thread owns 8-candidate chunks c with c%2==h; 64 chunks per tile
#pragma unroll 2
        for (int m = 0; m < TILE / 16; ++m) {
            const int g0 = 4 * m + 2 * h;    // float4 group index
            float4 xa = x4[g0], xb = x4[g0 + 1];
            float4 ya = y4[g0], yb = y4[g0 + 1];
            float4 za = z4[g0], zb = z4[g0 + 1];

            float d0, d1, d2, d3, d4, d5, d6, d7;
            dist2(pack2(xa.x, xa.y), pack2(ya.x, ya.y), pack2(za.x, za.y),
                  ncx2, ncy2, ncz2, d0, d1);
            dist2(pack2(xa.z, xa.w), pack2(ya.z, ya.w), pack2(za.z, za.w),
                  ncx2, ncy2, ncz2, d2, d3);
            dist2(pack2(xb.x, xb.y), pack2(yb.x, yb.y), pack2(zb.x, zb.y),
                  ncx2, ncy2, ncz2, d4, d5);
            dist2(pack2(xb.z, xb.w), pack2(yb.z, yb.w), pack2(zb.z, zb.w),
                  ncx2, ncy2, ncz2, d6, d7);

            const int j0 = tb + 4 * g0;      // first of 8 consecutive candidates
            // branch-free predicated pushes (@P STL.64 + @P IADD)
            if (d0 < tau) { lbuf[cnt] = make_float2(d0, __int_as_float(j0));     cnt++; }
            if (d1 < tau) { lbuf[cnt] = make_float2(d1, __int_as_float(j0 + 1)); cnt++; }
            if (d2 < tau) { lbuf[cnt] = make_float2(d2, __int_as_float(j0 + 2)); cnt++; }
            if (d3 < tau) { lbuf[cnt] = make_float2(d3, __int_as_float(j0 + 3)); cnt++; }
            if (d4 < tau) { lbuf[cnt] = make_float2(d4, __int_as_float(j0 + 4)); cnt++; }
            if (d5 < tau) { lbuf[cnt] = make_float2(d5, __int_as_float(j0 + 5)); cnt++; }
            if (d6 < tau) { lbuf[cnt] = make_float2(d6, __int_as_float(j0 + 6)); cnt++; }
            if (d7 < tau) { lbuf[cnt] = make_float2(d7, __int_as_float(j0 + 7)); cnt++; }

            // warp-synchronized flush: all lanes' inserts coalesce here
            if (__any_sync(0xffffffffu, cnt > BCAP - 8)) {
                for (int i = 0; i < cnt; ++i) {
                    float d = lbuf[i].x;
                    if (d < bd[NK - 1])
                        ins16(bd, bi, d, __float_as_int(lbuf[i].y));
                }
                cnt = 0;
                tau = bd[NK - 1];
            }
        }
    }

    // final flush
    for (int i = 0; i < cnt; ++i) {
        float d = lbuf[i].x;
        if (d < bd[NK - 1])
            ins16(bd, bi, d, __float_as_int(lbuf[i].y));
    }

    // -------- merge the two half-lists per query (exact, stable) ----------
    __syncthreads();                          // done reading tile smem
    float* md = (float*)smem_raw;             // 128*16 floats = 8KB
    int*   mi = (int*)(smem_raw + TPB * NK * 4);
#pragma unroll
    for (int k = 0; k < NK; ++k) { md[tid * NK + k] = bd[k]; mi[tid * NK + k] = bi[k]; }
    __syncthreads();

    if (h == 0) {
        const int pa = tid * NK, pb = pa + NK;
        int ia = 0, ib = 0;
        int fi_[NK];
#pragma unroll
        for (int k = 0; k < NK; ++k) {
            float da = md[pa + ia], db = md[pb + ib];
            int   ja = mi[pa + ia], jb = mi[pb + ib];
            bool ta = (da < db) || (da == db && ja < jb);   // lexicographic (d, idx)
            fi_[k] = ta ? ja : jb;
            if (ta) ia++; else ib++;
        }

        // rotation rows: frame[b,q,1:4,:]  (R[c][r] = fq[3 + c*3 + r])
        float R[3][3];
#pragma unroll
        for (int c = 0; c < 3; c++)
#pragma unroll
            for (int r = 0; r < 3; r++)
                R[c][r] = fq[3 + c * 3 + r];

        const size_t base = (size_t)q * NK;
        float* eo = eucl_out + base * 3;
#pragma unroll
        for (int k = 0; k < NK; ++k) {
            const int n = fi_[k];
            g_nbr[base + k] = n;
            const float* fn = fb + (size_t)n * 12;
            float d0 = fn[0] - cx;
            float d1 = fn[1] - cy;
            float d2 = fn[2] - cz;
            eo[k * 3 + 0] = d0 * R[0][0] + d1 * R[1][0] + d2 * R[2][0];
            eo[k * 3 + 1] = d0 * R[0][1] + d1 * R[1][1] + d2 * R[2][1];
            eo[k * 3 + 2] = d0 * R[0][2] + d1 * R[1][2] + d2 * R[2][2];
        }
    }
}

// ---------------------------------------------------------------------------
// Kernel 2: attribute gather (best measured config: 4 rows/warp, 8 lanes per
// row, 4 float4 per lane -> 44.8us).
// ---------------------------------------------------------------------------
__global__ __launch_bounds__(256, 8)
void gather_kernel(const float* __restrict__ attr,
                   float* __restrict__ gout)
{
    const int warp = (blockIdx.x * 256 + threadIdx.x) >> 5;
    const int lane = threadIdx.x & 31;
    const int row  = warp * 4 + (lane >> 3);      // 4 rows per warp
    const int l8   = lane & 7;

    const int b = row / (NL * NK);
    const int n = g_nbr[row];

    const float4* src = (const float4*)(attr + ((size_t)b * NL + n) * ND);
    float4*       dst = (float4*)(gout + (size_t)row * ND);

    float4 v0 = src[l8];
    float4 v1 = src[l8 + 8];
    float4 v2 = src[l8 + 16];
    float4 v3 = src[l8 + 24];
    dst[l8]      = v0;
    dst[l8 + 8]  = v1;
    dst[l8 + 16] = v2;
    dst[l8 + 24] = v3;
}

extern "C" void kernel_launch(void* const* d_in, const int* in_sizes, int n_in,
                              void* d_out, int out_size)
{
    const float* frame = (const float*)d_in[0];
    const float* attr  = (const float*)d_in[1];
    if (in_sizes[0] != NB * NL * 12) {
        frame = (const float*)d_in[1];
        attr  = (const float*)d_in[0];
    }

    float* eucl = (float*)d_out;                          // B*L*K*3 floats
    float* gath = (float*)d_out + (size_t)NB * NL * NK * 3;

    const int nq = NB * NL;                               // 32768 queries
    knn_kernel<<<nq / QPB, TPB>>>(frame, eucl);           // 512 blocks x 128

    const int rows = NB * NL * NK;                        // 524288
    gather_kernel<<<rows / 32, 256>>>(attr, gath);        // 4 rows/warp
}